// round 9
// baseline (speedup 1.0000x reference)
#include <cuda_runtime.h>
#include <cstdint>

// TPlanesEnc: B=4, N=131072, P=512, F=32.  M = B*N = 524288 points.
// d_in[0] = coords [B,N,3] fp32; d_in[1] = tplanes [3,P,P,F] fp32;
// d_out = [B,N,3F] fp32.
//
// R8: two passes to keep the hot texture L2-resident (R7 measured 504 MB
// DRAM = compulsory 310 MB + ~190 MB texture re-fetch; kernel is purely
// DRAM-bound at ~5 TB/s).
//   pass A: planes 0+1 fused (hot 64 MB < 126 MB L2), 2 pts/warp, 16 loads
//   pass B: plane 2 (hot 32 MB), 4 pts/warp, 16 loads
// Output stores stream (.cs). Warp-per-point-group, lane = channel.

#define PS 512
#define FD 32

__device__ __forceinline__ void stg_streaming(float* p, float v) {
    asm volatile("st.global.cs.f32 [%0], %1;" :: "l"(p), "f"(v) : "memory");
}

// ---------------- Pass A: planes 0 (x,y) and 1 (x,z), 2 points/warp -------
__global__ __launch_bounds__(256)
void pass01_kernel(const float* __restrict__ coords,
                   const float* __restrict__ tpl,
                   float* __restrict__ out,
                   int M)
{
    const int gtid  = blockIdx.x * blockDim.x + threadIdx.x;
    const int warp  = gtid >> 5;
    const int lane  = threadIdx.x & 31;
    const int pbase = warp * 2;
    if (pbase >= M) return;

    float cval = 0.0f;
    if (lane < 6) cval = __ldg(&coords[(size_t)pbase * 3 + lane]);

    const float* tbl = tpl + lane;  // lane = channel

    uint32_t off[16];
    float fx[2], fy[2], fz[2];

#pragma unroll
    for (int j = 0; j < 2; j++) {
        int i0[3], i1[3];
        float fr[3];
#pragma unroll
        for (int a = 0; a < 3; a++) {
            const float c = __shfl_sync(0xffffffffu, cval, j * 3 + a);
            float x = (c * 0.5f + 0.5f) * (float)PS - 0.5f;
            x = fminf(fmaxf(x, 0.0f), (float)(PS - 1));
            const float x0f = floorf(x);
            const int xi0 = (int)x0f;
            i0[a] = xi0;
            i1[a] = min(xi0 + 1, PS - 1);
            fr[a] = x - x0f;
        }
        fx[j] = fr[0]; fy[j] = fr[1]; fz[j] = fr[2];

        const uint32_t c0 = (uint32_t)i0[0] * FD;      // u = x for both planes
        const uint32_t c1 = (uint32_t)i1[0] * FD;
        // plane 0: v = y
        const uint32_t p0r0 = (uint32_t)i0[1] * (PS * FD);
        const uint32_t p0r1 = (uint32_t)i1[1] * (PS * FD);
        // plane 1: v = z
        const uint32_t p1r0 = (uint32_t)(PS * PS * FD) + (uint32_t)i0[2] * (PS * FD);
        const uint32_t p1r1 = (uint32_t)(PS * PS * FD) + (uint32_t)i1[2] * (PS * FD);

        off[j * 8 + 0] = p0r0 + c0;
        off[j * 8 + 1] = p0r0 + c1;
        off[j * 8 + 2] = p0r1 + c0;
        off[j * 8 + 3] = p0r1 + c1;
        off[j * 8 + 4] = p1r0 + c0;
        off[j * 8 + 5] = p1r0 + c1;
        off[j * 8 + 6] = p1r1 + c0;
        off[j * 8 + 7] = p1r1 + c1;
    }

    float tex[16];
#pragma unroll
    for (int i = 0; i < 16; i++) tex[i] = __ldg(tbl + off[i]);

#pragma unroll
    for (int j = 0; j < 2; j++) {
        float* op = out + (size_t)(pbase + j) * (3 * FD) + lane;
        // plane 0: fu = fx, fv = fy
        {
            const float f00 = tex[j * 8 + 0], f01 = tex[j * 8 + 1];
            const float f10 = tex[j * 8 + 2], f11 = tex[j * 8 + 3];
            const float top = f00 + (f01 - f00) * fx[j];
            const float bot = f10 + (f11 - f10) * fx[j];
            stg_streaming(op, top + (bot - top) * fy[j]);
        }
        // plane 1: fu = fx, fv = fz
        {
            const float f00 = tex[j * 8 + 4], f01 = tex[j * 8 + 5];
            const float f10 = tex[j * 8 + 6], f11 = tex[j * 8 + 7];
            const float top = f00 + (f01 - f00) * fx[j];
            const float bot = f10 + (f11 - f10) * fx[j];
            stg_streaming(op + FD, top + (bot - top) * fz[j]);
        }
    }
}

// ---------------- Pass B: plane 2 (u=z, v=y), 4 points/warp ----------------
__global__ __launch_bounds__(256)
void pass2_kernel(const float* __restrict__ coords,
                  const float* __restrict__ tpl,
                  float* __restrict__ out,
                  int M)
{
    const int gtid  = blockIdx.x * blockDim.x + threadIdx.x;
    const int warp  = gtid >> 5;
    const int lane  = threadIdx.x & 31;
    const int pbase = warp * 4;
    if (pbase >= M) return;

    float cval = 0.0f;
    if (lane < 12) cval = __ldg(&coords[(size_t)pbase * 3 + lane]);

    const float* tbl = tpl + (size_t)2 * PS * PS * FD + lane;

    uint32_t off[16];
    float fu[4], fv[4];

#pragma unroll
    for (int j = 0; j < 4; j++) {
        const float cz = __shfl_sync(0xffffffffu, cval, j * 3 + 2);
        const float cy = __shfl_sync(0xffffffffu, cval, j * 3 + 1);

        float u = (cz * 0.5f + 0.5f) * (float)PS - 0.5f;
        float v = (cy * 0.5f + 0.5f) * (float)PS - 0.5f;
        u = fminf(fmaxf(u, 0.0f), (float)(PS - 1));
        v = fminf(fmaxf(v, 0.0f), (float)(PS - 1));
        const float u0f = floorf(u);
        const float v0f = floorf(v);
        const int u0 = (int)u0f;
        const int v0 = (int)v0f;
        const int u1 = min(u0 + 1, PS - 1);
        const int v1 = min(v0 + 1, PS - 1);
        fu[j] = u - u0f;
        fv[j] = v - v0f;

        const uint32_t r0 = (uint32_t)v0 * (PS * FD);
        const uint32_t r1 = (uint32_t)v1 * (PS * FD);
        off[j * 4 + 0] = r0 + (uint32_t)u0 * FD;
        off[j * 4 + 1] = r0 + (uint32_t)u1 * FD;
        off[j * 4 + 2] = r1 + (uint32_t)u0 * FD;
        off[j * 4 + 3] = r1 + (uint32_t)u1 * FD;
    }

    float tex[16];
#pragma unroll
    for (int i = 0; i < 16; i++) tex[i] = __ldg(tbl + off[i]);

#pragma unroll
    for (int j = 0; j < 4; j++) {
        const float f00 = tex[j * 4 + 0], f01 = tex[j * 4 + 1];
        const float f10 = tex[j * 4 + 2], f11 = tex[j * 4 + 3];
        const float top = f00 + (f01 - f00) * fu[j];
        const float bot = f10 + (f11 - f10) * fu[j];
        stg_streaming(out + (size_t)(pbase + j) * (3 * FD) + 2 * FD + lane,
                      top + (bot - top) * fv[j]);
    }
}

extern "C" void kernel_launch(void* const* d_in, const int* in_sizes, int n_in,
                              void* d_out, int out_size)
{
    const float* coords = (const float*)d_in[0];
    const float* tpl    = (const float*)d_in[1];
    float* out          = (float*)d_out;

    const int M = in_sizes[0] / 3;  // total points = B*N

    const int blkA = (M + 15) / 16;   // 8 warps x 2 points
    const int blkB = (M + 31) / 32;   // 8 warps x 4 points
    pass01_kernel<<<blkA, 256>>>(coords, tpl, out, M);
    pass2_kernel <<<blkB, 256>>>(coords, tpl, out, M);
}

// round 10
// speedup vs baseline: 1.0265x; 1.0265x over previous
#include <cuda_runtime.h>
#include <cstdint>

// TPlanesEnc: B=4, N=131072, P=512, F=32.  M = B*N = 524288 points.
// d_in[0] = coords [B,N,3] fp32; d_in[1] = tplanes [3,P,P,F] fp32;
// d_out = [B,N,3F] fp32.
//
// R9: fused single pass (lowest instruction count per point; R8 proved
// per-plane passes are instruction-bound), 4 points per warp -> 48 texel
// loads in flight per warp. R1->R7 showed achieved DRAM BW rises with MLP
// (4.4 -> 5.0 TB/s); this pushes further toward the random-read ceiling.
// occ ~50% (2 CTAs x 256 thr, ~96 regs) traded for per-warp MLP.

#define PS 512
#define FD 32
#define PPW 4   // points per warp

__device__ __forceinline__ void stg_streaming(float* p, float v) {
    asm volatile("st.global.cs.f32 [%0], %1;" :: "l"(p), "f"(v) : "memory");
}

__global__ __launch_bounds__(256, 2)
void tplanes_kernel(const float* __restrict__ coords,
                    const float* __restrict__ tpl,
                    float* __restrict__ out,
                    int M)
{
    const int gtid  = blockIdx.x * blockDim.x + threadIdx.x;
    const int warp  = gtid >> 5;
    const int lane  = threadIdx.x & 31;
    const int pbase = warp * PPW;
    if (pbase >= M) return;

    // One coalesced coord fetch for 4 points (12 floats), spread by shuffle.
    float cval = 0.0f;
    if (lane < 3 * PPW) cval = __ldg(&coords[(size_t)pbase * 3 + lane]);

    const float* tbl = tpl + lane;  // lane = channel

    // plane 0 samples (u=x, v=y); plane 1 (u=x, v=z); plane 2 (u=z, v=y)
    uint32_t off[PPW * 12];
    float fu[PPW * 3], fv[PPW * 3];

#pragma unroll
    for (int j = 0; j < PPW; j++) {
        int i0[3], i1[3];
        float fr[3];
#pragma unroll
        for (int a = 0; a < 3; a++) {
            const float c = __shfl_sync(0xffffffffu, cval, j * 3 + a);
            float x = (c * 0.5f + 0.5f) * (float)PS - 0.5f;
            x = fminf(fmaxf(x, 0.0f), (float)(PS - 1));
            const float x0f = floorf(x);
            const int xi0 = (int)x0f;
            i0[a] = xi0;
            i1[a] = min(xi0 + 1, PS - 1);
            fr[a] = x - x0f;
        }

        const int uax[3] = {0, 0, 2};
        const int vax[3] = {1, 2, 1};
#pragma unroll
        for (int p = 0; p < 3; p++) {
            const uint32_t pb = (uint32_t)p * PS * PS * FD;
            const uint32_t r0 = pb + (uint32_t)i0[vax[p]] * (PS * FD);
            const uint32_t r1 = pb + (uint32_t)i1[vax[p]] * (PS * FD);
            const uint32_t c0 = (uint32_t)i0[uax[p]] * FD;
            const uint32_t c1 = (uint32_t)i1[uax[p]] * FD;
            off[j * 12 + p * 4 + 0] = r0 + c0;
            off[j * 12 + p * 4 + 1] = r0 + c1;
            off[j * 12 + p * 4 + 2] = r1 + c0;
            off[j * 12 + p * 4 + 3] = r1 + c1;
            fu[j * 3 + p] = fr[uax[p]];
            fv[j * 3 + p] = fr[vax[p]];
        }
    }

    // Issue all 48 texel loads back-to-back, then interpolate.
    float tex[PPW * 12];
#pragma unroll
    for (int i = 0; i < PPW * 12; i++) tex[i] = __ldg(tbl + off[i]);

#pragma unroll
    for (int j = 0; j < PPW; j++) {
        float* op = out + (size_t)(pbase + j) * (3 * FD) + lane;
#pragma unroll
        for (int p = 0; p < 3; p++) {
            const float f00 = tex[j * 12 + p * 4 + 0];
            const float f01 = tex[j * 12 + p * 4 + 1];
            const float f10 = tex[j * 12 + p * 4 + 2];
            const float f11 = tex[j * 12 + p * 4 + 3];
            const float x_ = fu[j * 3 + p];
            const float y_ = fv[j * 3 + p];
            const float top = f00 + (f01 - f00) * x_;
            const float bot = f10 + (f11 - f10) * x_;
            stg_streaming(op + p * FD, top + (bot - top) * y_);
        }
    }
}

extern "C" void kernel_launch(void* const* d_in, const int* in_sizes, int n_in,
                              void* d_out, int out_size)
{
    const float* coords = (const float*)d_in[0];
    const float* tpl    = (const float*)d_in[1];
    float* out          = (float*)d_out;

    const int M = in_sizes[0] / 3;                  // total points = B*N
    const int points_per_block = (256 / 32) * PPW;  // 32
    const int blocks = (M + points_per_block - 1) / points_per_block;
    tplanes_kernel<<<blocks, 256>>>(coords, tpl, out, M);
}